// round 16
// baseline (speedup 1.0000x reference)
#include <cuda_runtime.h>
#include <cuda_fp16.h>
#include <math.h>

#define VOCAB 32000
#define D_IN  512
#define D_H   1024
#define D3H   3072
#define D_OUT 64
#define BB    64
#define SS    256
#define NCTA  128

typedef unsigned long long u64t;
typedef unsigned int u32t;

// ---------------- scratch (static device globals; zero-init at load) ----------
// gi transposed: [3H rows][S*B cols]  (row = gate*1024+j, col = s*64+b)
__device__ float g_gi[(size_t)D3H * SS * BB];
// h fp32 transposed: [s][j][b]  (exact, consumed by fc and z-path)
__device__ float g_hs[(size_t)SS * D_H * BB];
__device__ float g_h0[D_H * BB];                // all-zero h(-1), never written
// MMA-ready fp16 h: word[k2*64+b] = (h[2k2][b], h[2k2+1][b])
__device__ u32t g_hmh[(D_H / 2) * BB];
__device__ u32t g_hmz[(D_H / 2) * BB];          // zeros (step 0)
// fp16 hi/lo splits (u32-packed k-pairs) for the HMMA gi GEMM
__device__ u32t g_embh[(size_t)VOCAB * (D_IN / 2)];
__device__ u32t g_embl[(size_t)VOCAB * (D_IN / 2)];
__device__ u32t g_wihh[(size_t)D3H * (D_IN / 2)];
__device__ u32t g_wihl[(size_t)D3H * (D_IN / 2)];

// ---------------- hierarchical grid barrier state (monotonic) ------------------
__device__ unsigned g_gcnt[8 * 64];             // group counters, 256B apart
__device__ unsigned g_ccnt = 0;                 // central counter (8 leaders/step)
__device__ volatile unsigned g_flag = 0;        // cumulative barriers passed

// ---------------- helpers -------------------------------------------------------
__device__ __forceinline__ void fma2(u64t& c, u64t a, u64t b) {
    asm("fma.rn.f32x2 %0, %1, %2, %0;" : "+l"(c) : "l"(a), "l"(b));
}
__device__ __forceinline__ float2 up2(u64t v) {
    float2 r;
    asm("mov.b64 {%0, %1}, %2;" : "=f"(r.x), "=f"(r.y) : "l"(v));
    return r;
}
__device__ __forceinline__ u64t dup64(float w) {
    u64t r;
    asm("mov.b64 %0, {%1, %1};" : "=l"(r) : "f"(w));
    return r;
}
// mma.sync m16n8k16 f16 -> f32 (sm_80 baseline PTX; compiles on base sm_103)
__device__ __forceinline__ void mma16816(float* d, u32t a0, u32t a1, u32t a2, u32t a3,
                                         u32t b0, u32t b1) {
    asm volatile(
        "mma.sync.aligned.m16n8k16.row.col.f32.f16.f16.f32 "
        "{%0,%1,%2,%3}, {%4,%5,%6,%7}, {%8,%9}, {%0,%1,%2,%3};"
        : "+f"(d[0]), "+f"(d[1]), "+f"(d[2]), "+f"(d[3])
        : "r"(a0), "r"(a1), "r"(a2), "r"(a3), "r"(b0), "r"(b1));
}

// ==============================================================================
// Kernel 0: fp32 -> packed fp16 hi/lo split (k-pair u32). Grid-stride over pairs.
// ==============================================================================
__global__ __launch_bounds__(256) void conv_split(
    const float* __restrict__ src, u32t* __restrict__ dh, u32t* __restrict__ dl,
    int n2)
{
    int i = blockIdx.x * blockDim.x + threadIdx.x;
    if (i < n2) {
        float2 v = ((const float2*)src)[i];
        __half h0 = __float2half_rn(v.x);
        __half l0 = __float2half_rn(v.x - __half2float(h0));
        __half h1 = __float2half_rn(v.y);
        __half l1 = __float2half_rn(v.y - __half2float(h1));
        dh[i] = (u32t)__half_as_ushort(h0) | ((u32t)__half_as_ushort(h1) << 16);
        dl[i] = (u32t)__half_as_ushort(l0) | ((u32t)__half_as_ushort(l1) << 16);
    }
}

// ==============================================================================
// Kernel 1: gi GEMM via HMMA hi/lo.   (FROZEN from R11)
// ==============================================================================
#define GAH 0
#define GAL 2560
#define GBH 5120
#define GBL 7680
#define GBUF 10240      // u32 per buffer; 2 buffers = 20480 u32 = 80 KB

__global__ void __launch_bounds__(256, 1) gi_hmma(
    const int* __restrict__ x, const float* __restrict__ b_ih)
{
    extern __shared__ u32t smw[];

    const int tid  = threadIdx.x;
    const int lane = tid & 31;
    const int wid  = tid >> 5;
    const int m_blk = blockIdx.y * 128;
    const int n_blk = blockIdx.x * 128;
    const int wm = wid & 1, wn = wid >> 1;

    const int r0 = tid >> 2, q4 = tid & 3;
    int n0 = n_blk + r0, n1 = n0 + 64;
    const size_t tok0 = (size_t)x[(n0 & 63) * SS + (n0 >> 6)] * 256;
    const size_t tok1 = (size_t)x[(n1 & 63) * SS + (n1 >> 6)] * 256;
    const size_t wr0 = (size_t)(m_blk + r0) * 256;
    const size_t wr1 = (size_t)(m_blk + r0 + 64) * 256;

    float d[4][4][4];
#pragma unroll
    for (int mt = 0; mt < 4; mt++)
#pragma unroll
        for (int nt = 0; nt < 4; nt++)
#pragma unroll
            for (int u = 0; u < 4; u++) d[mt][nt][u] = 0.f;

    {
        u32t* B = smw;
        *(uint4*)&B[GAH + r0 * 20 + q4 * 4]        = *(const uint4*)&g_wihh[wr0 + q4 * 4];
        *(uint4*)&B[GAH + (r0 + 64) * 20 + q4 * 4] = *(const uint4*)&g_wihh[wr1 + q4 * 4];
        *(uint4*)&B[GAL + r0 * 20 + q4 * 4]        = *(const uint4*)&g_wihl[wr0 + q4 * 4];
        *(uint4*)&B[GAL + (r0 + 64) * 20 + q4 * 4] = *(const uint4*)&g_wihl[wr1 + q4 * 4];
        *(uint4*)&B[GBH + r0 * 20 + q4 * 4]        = *(const uint4*)&g_embh[tok0 + q4 * 4];
        *(uint4*)&B[GBH + (r0 + 64) * 20 + q4 * 4] = *(const uint4*)&g_embh[tok1 + q4 * 4];
        *(uint4*)&B[GBL + r0 * 20 + q4 * 4]        = *(const uint4*)&g_embl[tok0 + q4 * 4];
        *(uint4*)&B[GBL + (r0 + 64) * 20 + q4 * 4] = *(const uint4*)&g_embl[tok1 + q4 * 4];
    }
    __syncthreads();

    for (int ch = 0; ch < 16; ch++) {
        uint4 va[4], vb[4];
        if (ch < 15) {
            int o = (ch + 1) * 16 + q4 * 4;
            va[0] = *(const uint4*)&g_wihh[wr0 + o];
            va[1] = *(const uint4*)&g_wihh[wr1 + o];
            va[2] = *(const uint4*)&g_wihl[wr0 + o];
            va[3] = *(const uint4*)&g_wihl[wr1 + o];
            vb[0] = *(const uint4*)&g_embh[tok0 + o];
            vb[1] = *(const uint4*)&g_embh[tok1 + o];
            vb[2] = *(const uint4*)&g_embl[tok0 + o];
            vb[3] = *(const uint4*)&g_embl[tok1 + o];
        }

        const u32t* S = smw + (ch & 1) * GBUF;
#pragma unroll
        for (int kt = 0; kt < 2; kt++) {
            const int k2b = kt * 8 + (lane & 3);
            u32t ah[4][4], al[4][4], bh[4][2], bl[4][2];
#pragma unroll
            for (int mt = 0; mt < 4; mt++) {
                int r = wm * 64 + mt * 16 + (lane >> 2);
                ah[mt][0] = S[GAH + r * 20 + k2b];
                ah[mt][1] = S[GAH + (r + 8) * 20 + k2b];
                ah[mt][2] = S[GAH + r * 20 + k2b + 4];
                ah[mt][3] = S[GAH + (r + 8) * 20 + k2b + 4];
                al[mt][0] = S[GAL + r * 20 + k2b];
                al[mt][1] = S[GAL + (r + 8) * 20 + k2b];
                al[mt][2] = S[GAL + r * 20 + k2b + 4];
                al[mt][3] = S[GAL + (r + 8) * 20 + k2b + 4];
            }
#pragma unroll
            for (int nt = 0; nt < 4; nt++) {
                int c = wn * 32 + nt * 8 + (lane >> 2);
                bh[nt][0] = S[GBH + c * 20 + k2b];
                bh[nt][1] = S[GBH + c * 20 + k2b + 4];
                bl[nt][0] = S[GBL + c * 20 + k2b];
                bl[nt][1] = S[GBL + c * 20 + k2b + 4];
            }
#pragma unroll
            for (int mt = 0; mt < 4; mt++)
#pragma unroll
                for (int nt = 0; nt < 4; nt++) {
                    mma16816(d[mt][nt], ah[mt][0], ah[mt][1], ah[mt][2], ah[mt][3],
                             bh[nt][0], bh[nt][1]);
                    mma16816(d[mt][nt], ah[mt][0], ah[mt][1], ah[mt][2], ah[mt][3],
                             bl[nt][0], bl[nt][1]);
                    mma16816(d[mt][nt], al[mt][0], al[mt][1], al[mt][2], al[mt][3],
                             bh[nt][0], bh[nt][1]);
                }
        }

        if (ch < 15) {
            u32t* B = smw + ((ch + 1) & 1) * GBUF;
            *(uint4*)&B[GAH + r0 * 20 + q4 * 4]        = va[0];
            *(uint4*)&B[GAH + (r0 + 64) * 20 + q4 * 4] = va[1];
            *(uint4*)&B[GAL + r0 * 20 + q4 * 4]        = va[2];
            *(uint4*)&B[GAL + (r0 + 64) * 20 + q4 * 4] = va[3];
            *(uint4*)&B[GBH + r0 * 20 + q4 * 4]        = vb[0];
            *(uint4*)&B[GBH + (r0 + 64) * 20 + q4 * 4] = vb[1];
            *(uint4*)&B[GBL + r0 * 20 + q4 * 4]        = vb[2];
            *(uint4*)&B[GBL + (r0 + 64) * 20 + q4 * 4] = vb[3];
            __syncthreads();
        }
    }

#pragma unroll
    for (int mt = 0; mt < 4; mt++) {
        int rlo = m_blk + wm * 64 + mt * 16 + (lane >> 2);
        float b0 = b_ih[rlo], b1 = b_ih[rlo + 8];
#pragma unroll
        for (int nt = 0; nt < 4; nt++) {
            int c = n_blk + wn * 32 + nt * 8 + 2 * (lane & 3);
            *(float2*)&g_gi[(size_t)rlo * (SS * BB) + c] =
                make_float2(d[mt][nt][0] + b0, d[mt][nt][1] + b0);
            *(float2*)&g_gi[(size_t)(rlo + 8) * (SS * BB) + c] =
                make_float2(d[mt][nt][2] + b1, d[mt][nt][3] + b1);
        }
    }
}

// ==============================================================================
// Kernel 2: PERSISTENT GRU, HMMA recurrence — direct-LDG fragments, fp16 h,
// fused 2-j epilogue (no ex bounce), hierarchical grid barrier.
// ==============================================================================
#define WH_O   0            // [512 k2][24] fp16x2 hi : 12288 words
#define WL_O   12288        // lo                     : 12288 words
#define RED_O  24576        // [4][64][30] float = 7680 words
#define SM_WORDS 32256      // 129024 bytes

// load chunk g's A fragments (2 its x {a0-3}) straight from global
__device__ __forceinline__ void ldA(const u32t* __restrict__ hmh,
                                    int g, int ks, int mtb, int lane, u32t* A)
{
#pragma unroll
    for (int it = 0; it < 2; it++) {
        int tl = ks + it * 4;
        int ka = tl * 8 + (lane & 3);
        const u32t* ph = hmh + (size_t)(g * 64 + ka) * 64 + mtb + (lane >> 2);
        A[it*4 + 0] = ph[0];
        A[it*4 + 1] = ph[8];
        A[it*4 + 2] = ph[256];          // (ka+4)*64
        A[it*4 + 3] = ph[264];
    }
}

__global__ void __launch_bounds__(512, 1) gru_persistent(
    const float* __restrict__ w_hh, const float* __restrict__ b_hh)
{
    extern __shared__ u32t smw[];
    float* redf = (float*)(smw + RED_O);

    const int tid  = threadIdx.x;
    const int cta  = blockIdx.x;
    const int grp  = cta >> 4;
    const int j0   = cta * 8;
    const int wid  = tid >> 5;
    const int lane = tid & 31;

    // ---- one-time: W slice -> fp16 hi/lo, layout [k2 global][24 n] ----
    {
        int k2 = tid;
#pragma unroll 1
        for (int n = 0; n < 24; n++) {
            int g = n >> 3, jj = n & 7;
            float2 wv = *(const float2*)(w_hh + (size_t)(g * D_H + j0 + jj) * D_H + k2 * 2);
            __half h0 = __float2half_rn(wv.x);
            __half l0 = __float2half_rn(wv.x - __half2float(h0));
            __half h1 = __float2half_rn(wv.y);
            __half l1 = __float2half_rn(wv.y - __half2float(h1));
            smw[WH_O + k2 * 24 + n] = (u32t)__half_as_ushort(h0) | ((u32t)__half_as_ushort(h1) << 16);
            smw[WL_O + k2 * 24 + n] = (u32t)__half_as_ushort(l0) | ((u32t)__half_as_ushort(l1) << 16);
        }
    }

    unsigned base = 0;
    if (tid == 0) base = g_flag;        // safe: flag advances only after all arrive
    __syncthreads();

    const int mt = wid & 3;
    const int ks = wid >> 2;
    const int mtb = mt * 16;
    const int ncol = lane >> 2;
    // fused epilogue identity (tid < 256): j pair (j0+2ek, j0+2ek+1), batch eb
    const int ek = tid >> 6, eb = tid & 63;
    const int ej0 = j0 + 2 * ek, ej1 = ej0 + 1;
    const float bhr0 = b_hh[ej0],          bhr1 = b_hh[ej1];
    const float bhz0 = b_hh[D_H + ej0],    bhz1 = b_hh[D_H + ej1];
    const float bhn0 = b_hh[2*D_H + ej0],  bhn1 = b_hh[2*D_H + ej1];

    for (int s = 0; s < SS; s++) {
        const float* hp32 = (s == 0) ? g_h0 : (g_hs + (size_t)(s - 1) * D_H * BB);
        const u32t* hmh = (s == 0) ? g_hmz : g_hmh;

        // ---- chunk 0 fragment loads first (post-barrier critical path) ----
        u32t A[2][8];
        ldA(hmh, 0, ks, mtb, lane, A[0]);

        // ---- epilogue operand prefetch (tid < 256: 2 outputs each) ----
        float e_gir0, e_giz0, e_gin0, e_hp0;
        float e_gir1, e_giz1, e_gin1, e_hp1;
        if (tid < 256) {
            const float* gp0 = g_gi + (size_t)s * 64 + (size_t)ej0 * (SS * BB) + eb;
            const float* gp1 = gp0 + (size_t)(SS * BB);
            e_gir0 = gp0[0];
            e_giz0 = gp0[(size_t)D_H * SS * BB];
            e_gin0 = gp0[(size_t)2 * D_H * SS * BB];
            e_gir1 = gp1[0];
            e_giz1 = gp1[(size_t)D_H * SS * BB];
            e_gin1 = gp1[(size_t)2 * D_H * SS * BB];
            e_hp0  = hp32[(size_t)ej0 * 64 + eb];
            e_hp1  = hp32[(size_t)ej1 * 64 + eb];
        }

        float d[3][4];
#pragma unroll
        for (int nt = 0; nt < 3; nt++)
#pragma unroll
            for (int u = 0; u < 4; u++) d[nt][u] = 0.f;

#pragma unroll
        for (int g = 0; g < 8; g++) {
            if (g < 7) ldA(hmh, g + 1, ks, mtb, lane, A[(g + 1) & 1]);

            const u32t* Ac = A[g & 1];
#pragma unroll
            for (int it = 0; it < 2; it++) {
                int tl = ks + it * 4;
                int ka = tl * 8 + (lane & 3);
                int kw = (g * 64 + ka) * 24 + ncol;
#pragma unroll
                for (int nt = 0; nt < 3; nt++) {
                    u32t bh0 = smw[WH_O + kw + nt * 8];
                    u32t bh1 = smw[WH_O + kw + 96 + nt * 8];
                    u32t bl0 = smw[WL_O + kw + nt * 8];
                    u32t bl1 = smw[WL_O + kw + 96 + nt * 8];
                    mma16816(d[nt], Ac[it*4+0], Ac[it*4+1], Ac[it*4+2], Ac[it*4+3],
                             bh0, bh1);
                    mma16816(d[nt], Ac[it*4+0], Ac[it*4+1], Ac[it*4+2], Ac[it*4+3],
                             bl0, bl1);
                }
            }
        }

        // ---- D fragments -> red [4 ks][64 m][30 n-pad] ----
#pragma unroll
        for (int nt = 0; nt < 3; nt++) {
            int rb = (ks * 64 + mt * 16 + (lane >> 2)) * 30 + nt * 8 + 2 * (lane & 3);
            *(float2*)&redf[rb]       = make_float2(d[nt][0], d[nt][1]);
            *(float2*)&redf[rb + 240] = make_float2(d[nt][2], d[nt][3]);
        }
        __syncthreads();

        // ---- fused gate epilogue + MMA-word pack (tid < 256, 2 j's each) ----
        if (tid < 256) {
            float ghr0 = 0.f, ghz0 = 0.f, ghn0 = 0.f;
            float ghr1 = 0.f, ghz1 = 0.f, ghn1 = 0.f;
#pragma unroll
            for (int k = 0; k < 4; k++) {
                int rb = (k * 64 + eb) * 30;
                ghr0 += redf[rb + 2*ek];        ghr1 += redf[rb + 2*ek + 1];
                ghz0 += redf[rb + 8 + 2*ek];    ghz1 += redf[rb + 8 + 2*ek + 1];
                ghn0 += redf[rb + 16 + 2*ek];   ghn1 += redf[rb + 16 + 2*ek + 1];
            }
            float r0 = 1.f / (1.f + expf(-(e_gir0 + ghr0 + bhr0)));
            float z0 = 1.f / (1.f + expf(-(e_giz0 + ghz0 + bhz0)));
            float n0 = tanhf(e_gin0 + r0 * (ghn0 + bhn0));
            float h0 = (1.f - z0) * n0 + z0 * e_hp0;
            float r1 = 1.f / (1.f + expf(-(e_gir1 + ghr1 + bhr1)));
            float z1 = 1.f / (1.f + expf(-(e_giz1 + ghz1 + bhz1)));
            float n1 = tanhf(e_gin1 + r1 * (ghn1 + bhn1));
            float h1 = (1.f - z1) * n1 + z1 * e_hp1;

            float* hout = g_hs + (size_t)s * D_H * BB;
            hout[(size_t)ej0 * 64 + eb] = h0;
            hout[(size_t)ej1 * 64 + eb] = h1;

            u32t wh = (u32t)__half_as_ushort(__float2half_rn(h0))
                    | ((u32t)__half_as_ushort(__float2half_rn(h1)) << 16);
            g_hmh[(4 * cta + ek) * 64 + eb] = wh;
        }

        // ---- hierarchical grid barrier (monotonic flag, 2-level arrival) ----
        __syncthreads();
        if (tid == 0) {
            __threadfence();
            unsigned target = base + (unsigned)(s + 1);
            unsigned old = atomicAdd(&g_gcnt[grp * 64], 1u);
            if (old == 16u * target - 1u) {
                unsigned oc = atomicAdd(&g_ccnt, 1u);
                if (oc == 8u * target - 1u) {
                    __threadfence();
                    atomicExch((unsigned*)&g_flag, target);
                } else {
                    while (g_flag < target) { }
                }
            } else {
                while (g_flag < target) { }
            }
            __threadfence();
        }
        __syncthreads();
    }
}

// ==============================================================================
// Kernel 3: fc + log_softmax (unchanged)
// ==============================================================================
__global__ __launch_bounds__(256) void fc_lsm(
    const float* __restrict__ fc_w, const float* __restrict__ fc_b,
    float* __restrict__ out)
{
    __shared__ float hst[32 * 64];
    __shared__ float wst[64 * 36];
    __shared__ float L  [64 * 65];

    const int tid = threadIdx.x;
    const int s   = blockIdx.x;
    const float* hs_s = g_hs + (size_t)s * D_H * BB;
    const int og = tid & 15, bg = tid >> 4;

    u64t acc[2][4];
#pragma unroll
    for (int u = 0; u < 2; u++)
#pragma unroll
        for (int v = 0; v < 4; v++) acc[u][v] = 0ull;
    u64t* hst8 = (u64t*)hst;

    for (int k0 = 0; k0 < D_H; k0 += 32) {
        __syncthreads();
#pragma unroll
        for (int i = 0; i < 2; i++) {
            int q = tid + i * 256;
            int kl = q >> 4, bq = q & 15;
            *(float4*)(hst + kl*64 + bq*4) =
                *(const float4*)(hs_s + (size_t)(k0 + kl) * 64 + bq * 4);
        }
#pragma unroll
        for (int i = 0; i < 2; i++) {
            int q = tid + i * 256;
            int o = q >> 3, kq = q & 7;
            *(float4*)(wst + o*36 + kq*4) =
                *(const float4*)(fc_w + (size_t)o * D_H + k0 + kq * 4);
        }
        __syncthreads();
#pragma unroll 4
        for (int kk = 0; kk < 32; kk++) {
            u64t h0 = hst8[kk*32 + bg*2 + 0];
            u64t h1 = hst8[kk*32 + bg*2 + 1];
#pragma unroll
            for (int v = 0; v < 4; v++) {
                u64t wd = dup64(wst[(og*4 + v)*36 + kk]);
                fma2(acc[0][v], h0, wd);
                fma2(acc[1][v], h1, wd);
            }
        }
    }

    __syncthreads();
#pragma unroll
    for (int u = 0; u < 2; u++) {
#pragma unroll
        for (int v = 0; v < 4; v++) {
            float2 p = up2(acc[u][v]);
            int o  = og * 4 + v;
            int b0 = bg * 4 + u * 2;
            float bias = fc_b[o];
            L[(b0 + 0)*65 + o] = p.x + bias;
            L[(b0 + 1)*65 + o] = p.y + bias;
        }
    }
    __syncthreads();

    const int w = tid >> 5, lane = tid & 31;
#pragma unroll
    for (int rr = 0; rr < 8; rr++) {
        int b = w * 8 + rr;
        float v0 = L[b*65 + lane], v1 = L[b*65 + 32 + lane];
        float mx = fmaxf(v0, v1);
#pragma unroll
        for (int o = 16; o > 0; o >>= 1) mx = fmaxf(mx, __shfl_xor_sync(0xffffffffu, mx, o));
        float se = expf(v0 - mx) + expf(v1 - mx);
#pragma unroll
        for (int o = 16; o > 0; o >>= 1) se += __shfl_xor_sync(0xffffffffu, se, o);
        float lse = logf(se) + mx;
        float* op = out + ((size_t)b * SS + s) * D_OUT;
        op[lane]      = v0 - lse;
        op[lane + 32] = v1 - lse;
    }
}

// ==============================================================================
extern "C" void kernel_launch(void* const* d_in, const int* in_sizes, int n_in,
                              void* d_out, int out_size)
{
    (void)in_sizes; (void)n_in; (void)out_size;
    const int*   x    = (const int*)  d_in[0];
    const float* emb  = (const float*)d_in[1];
    const float* w_ih = (const float*)d_in[2];
    const float* w_hh = (const float*)d_in[3];
    const float* b_ih = (const float*)d_in[4];
    const float* b_hh = (const float*)d_in[5];
    const float* fc_w = (const float*)d_in[6];
    const float* fc_b = (const float*)d_in[7];
    float* out = (float*)d_out;

    const int rec_smem = SM_WORDS * 4;   // 129024 B
    cudaFuncSetAttribute(gru_persistent,
                         cudaFuncAttributeMaxDynamicSharedMemorySize, rec_smem);
    const int gi_smem = 2 * GBUF * 4;    // 81920 B
    cudaFuncSetAttribute(gi_hmma,
                         cudaFuncAttributeMaxDynamicSharedMemorySize, gi_smem);

    u32t *embh, *embl, *wihh, *wihl;
    cudaGetSymbolAddress((void**)&embh, g_embh);
    cudaGetSymbolAddress((void**)&embl, g_embl);
    cudaGetSymbolAddress((void**)&wihh, g_wihh);
    cudaGetSymbolAddress((void**)&wihl, g_wihl);

    conv_split<<<(VOCAB * 256 + 255) / 256, 256>>>(emb, embh, embl, VOCAB * 256);
    conv_split<<<(D3H * 256 + 255) / 256, 256>>>(w_ih, wihh, wihl, D3H * 256);
    gi_hmma<<<dim3((SS * BB) / 128, D3H / 128), 256, gi_smem>>>(x, b_ih);
    gru_persistent<<<NCTA, 512, rec_smem>>>(w_hh, b_hh);
    fc_lsm<<<SS, 256>>>(fc_w, fc_b, out);
}

// round 17
// speedup vs baseline: 1.0890x; 1.0890x over previous
#include <cuda_runtime.h>
#include <cuda_fp16.h>
#include <math.h>

#define VOCAB 32000
#define D_IN  512
#define D_H   1024
#define D3H   3072
#define D_OUT 64
#define BB    64
#define SS    256
#define NCTA  128

typedef unsigned long long u64t;
typedef unsigned int u32t;

// ---------------- scratch (static device globals; zero-init at load) ----------
// gi transposed: [3H rows][S*B cols]  (row = gate*1024+j, col = s*64+b)
__device__ float g_gi[(size_t)D3H * SS * BB];
// h fp32 transposed: [s][j][b]  (exact, consumed by fc and z-path)
__device__ float g_hs[(size_t)SS * D_H * BB];
__device__ float g_h0[D_H * BB];                // all-zero h(-1), never written
// MMA-ready fp16 h: word[k2*64+b] = (h[2k2][b], h[2k2+1][b])
__device__ u32t g_hmh[(D_H / 2) * BB];
__device__ u32t g_hmz[(D_H / 2) * BB];          // zeros (step 0)
// fp16 splits for the HMMA gi GEMM: emb hi only; w_ih hi+lo
__device__ u32t g_embh[(size_t)VOCAB * (D_IN / 2)];
__device__ u32t g_wihh[(size_t)D3H * (D_IN / 2)];
__device__ u32t g_wihl[(size_t)D3H * (D_IN / 2)];

// ---------------- grid barrier state (R15-proven central protocol) -------------
__device__ unsigned g_cnt = 0;
__device__ volatile unsigned g_flag = 0;        // cumulative barriers passed (monotonic)

// ---------------- helpers -------------------------------------------------------
__device__ __forceinline__ void fma2(u64t& c, u64t a, u64t b) {
    asm("fma.rn.f32x2 %0, %1, %2, %0;" : "+l"(c) : "l"(a), "l"(b));
}
__device__ __forceinline__ float2 up2(u64t v) {
    float2 r;
    asm("mov.b64 {%0, %1}, %2;" : "=f"(r.x), "=f"(r.y) : "l"(v));
    return r;
}
__device__ __forceinline__ u64t dup64(float w) {
    u64t r;
    asm("mov.b64 %0, {%1, %1};" : "=l"(r) : "f"(w));
    return r;
}
// mma.sync m16n8k16 f16 -> f32 (sm_80 baseline PTX; compiles on base sm_103)
__device__ __forceinline__ void mma16816(float* d, u32t a0, u32t a1, u32t a2, u32t a3,
                                         u32t b0, u32t b1) {
    asm volatile(
        "mma.sync.aligned.m16n8k16.row.col.f32.f16.f16.f32 "
        "{%0,%1,%2,%3}, {%4,%5,%6,%7}, {%8,%9}, {%0,%1,%2,%3};"
        : "+f"(d[0]), "+f"(d[1]), "+f"(d[2]), "+f"(d[3])
        : "r"(a0), "r"(a1), "r"(a2), "r"(a3), "r"(b0), "r"(b1));
}

// ==============================================================================
// Kernel 0a: fp32 -> packed fp16 hi/lo split (k-pair u32).  (w_ih)
// ==============================================================================
__global__ __launch_bounds__(256) void conv_split(
    const float* __restrict__ src, u32t* __restrict__ dh, u32t* __restrict__ dl,
    int n2)
{
    int i = blockIdx.x * blockDim.x + threadIdx.x;
    if (i < n2) {
        float2 v = ((const float2*)src)[i];
        __half h0 = __float2half_rn(v.x);
        __half l0 = __float2half_rn(v.x - __half2float(h0));
        __half h1 = __float2half_rn(v.y);
        __half l1 = __float2half_rn(v.y - __half2float(h1));
        dh[i] = (u32t)__half_as_ushort(h0) | ((u32t)__half_as_ushort(h1) << 16);
        dl[i] = (u32t)__half_as_ushort(l0) | ((u32t)__half_as_ushort(l1) << 16);
    }
}

// ==============================================================================
// Kernel 0b: fp32 -> packed fp16 hi only (k-pair u32).  (emb)
// ==============================================================================
__global__ __launch_bounds__(256) void conv_hi(
    const float* __restrict__ src, u32t* __restrict__ dh, int n2)
{
    int i = blockIdx.x * blockDim.x + threadIdx.x;
    if (i < n2) {
        float2 v = ((const float2*)src)[i];
        __half h0 = __float2half_rn(v.x);
        __half h1 = __float2half_rn(v.y);
        dh[i] = (u32t)__half_as_ushort(h0) | ((u32t)__half_as_ushort(h1) << 16);
    }
}

// ==============================================================================
// Kernel 1: gi GEMM via HMMA — w_ih hi+lo x emb hi (2 products).
// g_gi[m][n] = sum_d w_ih[m][d] * emb[x(n)][d] + b_ih[m]
// M=3072, N=16384 tokens, K=512. Tile 128x128xK, 16 chunks of 32.
// 256 threads = 8 warps (2M x 4N), warp tile 64x32, m16n8k16.
// SMEM row-major [row][k2] pad 20 (conflict-free fragment loads).
// ==============================================================================
#define GAH 0
#define GAL 2560
#define GBH 5120
#define GBUF 7680       // u32 per buffer; 2 buffers = 15360 u32 = 60 KB

__global__ void __launch_bounds__(256, 1) gi_hmma(
    const int* __restrict__ x, const float* __restrict__ b_ih)
{
    extern __shared__ u32t smw[];

    const int tid  = threadIdx.x;
    const int lane = tid & 31;
    const int wid  = tid >> 5;
    const int m_blk = blockIdx.y * 128;
    const int n_blk = blockIdx.x * 128;
    const int wm = wid & 1, wn = wid >> 1;

    const int r0 = tid >> 2, q4 = tid & 3;
    int n0 = n_blk + r0, n1 = n0 + 64;
    const size_t tok0 = (size_t)x[(n0 & 63) * SS + (n0 >> 6)] * 256;
    const size_t tok1 = (size_t)x[(n1 & 63) * SS + (n1 >> 6)] * 256;
    const size_t wr0 = (size_t)(m_blk + r0) * 256;
    const size_t wr1 = (size_t)(m_blk + r0 + 64) * 256;

    float d[4][4][4];
#pragma unroll
    for (int mt = 0; mt < 4; mt++)
#pragma unroll
        for (int nt = 0; nt < 4; nt++)
#pragma unroll
            for (int u = 0; u < 4; u++) d[mt][nt][u] = 0.f;

    {
        u32t* B = smw;
        *(uint4*)&B[GAH + r0 * 20 + q4 * 4]        = *(const uint4*)&g_wihh[wr0 + q4 * 4];
        *(uint4*)&B[GAH + (r0 + 64) * 20 + q4 * 4] = *(const uint4*)&g_wihh[wr1 + q4 * 4];
        *(uint4*)&B[GAL + r0 * 20 + q4 * 4]        = *(const uint4*)&g_wihl[wr0 + q4 * 4];
        *(uint4*)&B[GAL + (r0 + 64) * 20 + q4 * 4] = *(const uint4*)&g_wihl[wr1 + q4 * 4];
        *(uint4*)&B[GBH + r0 * 20 + q4 * 4]        = *(const uint4*)&g_embh[tok0 + q4 * 4];
        *(uint4*)&B[GBH + (r0 + 64) * 20 + q4 * 4] = *(const uint4*)&g_embh[tok1 + q4 * 4];
    }
    __syncthreads();

    for (int ch = 0; ch < 16; ch++) {
        uint4 va[4], vb[2];
        if (ch < 15) {
            int o = (ch + 1) * 16 + q4 * 4;
            va[0] = *(const uint4*)&g_wihh[wr0 + o];
            va[1] = *(const uint4*)&g_wihh[wr1 + o];
            va[2] = *(const uint4*)&g_wihl[wr0 + o];
            va[3] = *(const uint4*)&g_wihl[wr1 + o];
            vb[0] = *(const uint4*)&g_embh[tok0 + o];
            vb[1] = *(const uint4*)&g_embh[tok1 + o];
        }

        const u32t* S = smw + (ch & 1) * GBUF;
#pragma unroll
        for (int kt = 0; kt < 2; kt++) {
            const int k2b = kt * 8 + (lane & 3);
            u32t ah[4][4], al[4][4], bh[4][2];
#pragma unroll
            for (int mt = 0; mt < 4; mt++) {
                int r = wm * 64 + mt * 16 + (lane >> 2);
                ah[mt][0] = S[GAH + r * 20 + k2b];
                ah[mt][1] = S[GAH + (r + 8) * 20 + k2b];
                ah[mt][2] = S[GAH + r * 20 + k2b + 4];
                ah[mt][3] = S[GAH + (r + 8) * 20 + k2b + 4];
                al[mt][0] = S[GAL + r * 20 + k2b];
                al[mt][1] = S[GAL + (r + 8) * 20 + k2b];
                al[mt][2] = S[GAL + r * 20 + k2b + 4];
                al[mt][3] = S[GAL + (r + 8) * 20 + k2b + 4];
            }
#pragma unroll
            for (int nt = 0; nt < 4; nt++) {
                int c = wn * 32 + nt * 8 + (lane >> 2);
                bh[nt][0] = S[GBH + c * 20 + k2b];
                bh[nt][1] = S[GBH + c * 20 + k2b + 4];
            }
#pragma unroll
            for (int mt = 0; mt < 4; mt++)
#pragma unroll
                for (int nt = 0; nt < 4; nt++) {
                    mma16816(d[mt][nt], ah[mt][0], ah[mt][1], ah[mt][2], ah[mt][3],
                             bh[nt][0], bh[nt][1]);
                    mma16816(d[mt][nt], al[mt][0], al[mt][1], al[mt][2], al[mt][3],
                             bh[nt][0], bh[nt][1]);
                }
        }

        if (ch < 15) {
            u32t* B = smw + ((ch + 1) & 1) * GBUF;
            *(uint4*)&B[GAH + r0 * 20 + q4 * 4]        = va[0];
            *(uint4*)&B[GAH + (r0 + 64) * 20 + q4 * 4] = va[1];
            *(uint4*)&B[GAL + r0 * 20 + q4 * 4]        = va[2];
            *(uint4*)&B[GAL + (r0 + 64) * 20 + q4 * 4] = va[3];
            *(uint4*)&B[GBH + r0 * 20 + q4 * 4]        = vb[0];
            *(uint4*)&B[GBH + (r0 + 64) * 20 + q4 * 4] = vb[1];
            __syncthreads();
        }
    }

#pragma unroll
    for (int mt = 0; mt < 4; mt++) {
        int rlo = m_blk + wm * 64 + mt * 16 + (lane >> 2);
        float b0 = b_ih[rlo], b1 = b_ih[rlo + 8];
#pragma unroll
        for (int nt = 0; nt < 4; nt++) {
            int c = n_blk + wn * 32 + nt * 8 + 2 * (lane & 3);
            *(float2*)&g_gi[(size_t)rlo * (SS * BB) + c] =
                make_float2(d[mt][nt][0] + b0, d[mt][nt][1] + b0);
            *(float2*)&g_gi[(size_t)(rlo + 8) * (SS * BB) + c] =
                make_float2(d[mt][nt][2] + b1, d[mt][nt][3] + b1);
        }
    }
}

// ==============================================================================
// Kernel 2: PERSISTENT GRU, HMMA recurrence.  (FROZEN byte-exact from R15)
// ==============================================================================
#define WH_O   0            // [512 k2][24] fp16x2 hi : 12288 words
#define WL_O   12288        // lo                     : 12288 words
#define RED_O  24576        // [4][64][30] float = 7680 words
#define EX_O   32256        // ushort ex_h[512] = 256 words
#define SM_WORDS 32768      // 131072 bytes

// load chunk g's A fragments (2 its x {a0-3}) straight from global
__device__ __forceinline__ void ldA(const u32t* __restrict__ hmh,
                                    int g, int ks, int mtb, int lane, u32t* A)
{
#pragma unroll
    for (int it = 0; it < 2; it++) {
        int tl = ks + it * 4;
        int ka = tl * 8 + (lane & 3);
        const u32t* ph = hmh + (size_t)(g * 64 + ka) * 64 + mtb + (lane >> 2);
        A[it*4 + 0] = ph[0];
        A[it*4 + 1] = ph[8];
        A[it*4 + 2] = ph[256];          // (ka+4)*64
        A[it*4 + 3] = ph[264];
    }
}

__global__ void __launch_bounds__(512, 1) gru_persistent(
    const float* __restrict__ w_hh, const float* __restrict__ b_hh)
{
    extern __shared__ u32t smw[];
    float* redf = (float*)(smw + RED_O);
    unsigned short* ex = (unsigned short*)(smw + EX_O);   // ex_h[512]

    const int tid  = threadIdx.x;
    const int j0   = blockIdx.x * 8;
    const int wid  = tid >> 5;
    const int lane = tid & 31;

    // ---- one-time: W slice -> fp16 hi/lo, layout [k2 global][24 n] ----
    {
        int k2 = tid;
#pragma unroll 1
        for (int n = 0; n < 24; n++) {
            int g = n >> 3, jj = n & 7;
            float2 wv = *(const float2*)(w_hh + (size_t)(g * D_H + j0 + jj) * D_H + k2 * 2);
            __half h0 = __float2half_rn(wv.x);
            __half l0 = __float2half_rn(wv.x - __half2float(h0));
            __half h1 = __float2half_rn(wv.y);
            __half l1 = __float2half_rn(wv.y - __half2float(h1));
            smw[WH_O + k2 * 24 + n] = (u32t)__half_as_ushort(h0) | ((u32t)__half_as_ushort(h1) << 16);
            smw[WL_O + k2 * 24 + n] = (u32t)__half_as_ushort(l0) | ((u32t)__half_as_ushort(l1) << 16);
        }
    }

    unsigned base = 0;
    if (tid == 0) base = g_flag;
    __syncthreads();

    const int mt = wid & 3;
    const int ks = wid >> 2;
    const int mtb = mt * 16;
    const int ncol = lane >> 2;
    const int ejj = tid >> 6, eb = tid & 63;
    const int ej  = j0 + ejj;
    const float bhr = b_hh[ej], bhz = b_hh[D_H + ej], bhn = b_hh[2 * D_H + ej];

    for (int s = 0; s < SS; s++) {
        const float* hp32 = (s == 0) ? g_h0 : (g_hs + (size_t)(s - 1) * D_H * BB);
        const u32t* hmh = (s == 0) ? g_hmz : g_hmh;

        // ---- chunk 0 fragment loads first (post-barrier critical path) ----
        u32t A[2][8];
        ldA(hmh, 0, ks, mtb, lane, A[0]);

        // ---- epilogue operand prefetch (overlaps) ----
        const float* gip = g_gi + (size_t)s * 64 + (size_t)ej * (SS * BB) + eb;
        float e_gir = gip[0];
        float e_giz = gip[(size_t)D_H * SS * BB];
        float e_gin = gip[(size_t)2 * D_H * SS * BB];
        float e_hp  = hp32[(size_t)ej * 64 + eb];

        float d[3][4];
#pragma unroll
        for (int nt = 0; nt < 3; nt++)
#pragma unroll
            for (int u = 0; u < 4; u++) d[nt][u] = 0.f;

#pragma unroll
        for (int g = 0; g < 8; g++) {
            if (g < 7) ldA(hmh, g + 1, ks, mtb, lane, A[(g + 1) & 1]);

            const u32t* Ac = A[g & 1];
#pragma unroll
            for (int it = 0; it < 2; it++) {
                int tl = ks + it * 4;
                int ka = tl * 8 + (lane & 3);
                int kw = (g * 64 + ka) * 24 + ncol;
#pragma unroll
                for (int nt = 0; nt < 3; nt++) {
                    u32t bh0 = smw[WH_O + kw + nt * 8];
                    u32t bh1 = smw[WH_O + kw + 96 + nt * 8];
                    u32t bl0 = smw[WL_O + kw + nt * 8];
                    u32t bl1 = smw[WL_O + kw + 96 + nt * 8];
                    mma16816(d[nt], Ac[it*4+0], Ac[it*4+1], Ac[it*4+2], Ac[it*4+3],
                             bh0, bh1);
                    mma16816(d[nt], Ac[it*4+0], Ac[it*4+1], Ac[it*4+2], Ac[it*4+3],
                             bl0, bl1);
                }
            }
        }

        // ---- D fragments -> red [4 ks][64 m][30 n-pad] ----
#pragma unroll
        for (int nt = 0; nt < 3; nt++) {
            int rb = (ks * 64 + mt * 16 + (lane >> 2)) * 30 + nt * 8 + 2 * (lane & 3);
            *(float2*)&redf[rb]       = make_float2(d[nt][0], d[nt][1]);
            *(float2*)&redf[rb + 240] = make_float2(d[nt][2], d[nt][3]);
        }
        __syncthreads();

        // ---- gate epilogue: 512 outputs, 1 per thread ----
        {
            float ghr = 0.f, ghz = 0.f, ghn = 0.f;
#pragma unroll
            for (int k = 0; k < 4; k++) {
                int rb = (k * 64 + eb) * 30;
                ghr += redf[rb + ejj];
                ghz += redf[rb + 8 + ejj];
                ghn += redf[rb + 16 + ejj];
            }
            float r = 1.f / (1.f + expf(-(e_gir + ghr + bhr)));
            float z = 1.f / (1.f + expf(-(e_giz + ghz + bhz)));
            float n = tanhf(e_gin + r * (ghn + bhn));
            float h = (1.f - z) * n + z * e_hp;
            g_hs[(size_t)s * D_H * BB + (size_t)ej * 64 + eb] = h;
            ex[ejj * 64 + eb] = __half_as_ushort(__float2half_rn(h));
        }
        __syncthreads();

        // ---- pack MMA-ready words: word(k2, b) = (h[2k2][b], h[2k2+1][b]) ----
        if (tid < 256) {
            int k2l = tid >> 6, b = tid & 63;
            u32t wh = (u32t)ex[(2 * k2l) * 64 + b]
                    | ((u32t)ex[(2 * k2l + 1) * 64 + b] << 16);
            int k2g = 4 * blockIdx.x + k2l;
            g_hmh[k2g * 64 + b] = wh;
        }

        // ---- grid barrier (proven) ----
        __syncthreads();
        if (tid == 0) {
            __threadfence();
            unsigned target = base + (unsigned)(s + 1);
            unsigned old = atomicAdd(&g_cnt, 1u);
            if (old == NCTA - 1) {
                atomicExch(&g_cnt, 0u);
                __threadfence();
                atomicExch((unsigned*)&g_flag, target);
            } else {
                while (g_flag < target) { }
            }
            __threadfence();
        }
        __syncthreads();
    }
}

// ==============================================================================
// Kernel 3: fc + log_softmax (unchanged)
// ==============================================================================
__global__ __launch_bounds__(256) void fc_lsm(
    const float* __restrict__ fc_w, const float* __restrict__ fc_b,
    float* __restrict__ out)
{
    __shared__ float hst[32 * 64];
    __shared__ float wst[64 * 36];
    __shared__ float L  [64 * 65];

    const int tid = threadIdx.x;
    const int s   = blockIdx.x;
    const float* hs_s = g_hs + (size_t)s * D_H * BB;
    const int og = tid & 15, bg = tid >> 4;

    u64t acc[2][4];
#pragma unroll
    for (int u = 0; u < 2; u++)
#pragma unroll
        for (int v = 0; v < 4; v++) acc[u][v] = 0ull;
    u64t* hst8 = (u64t*)hst;

    for (int k0 = 0; k0 < D_H; k0 += 32) {
        __syncthreads();
#pragma unroll
        for (int i = 0; i < 2; i++) {
            int q = tid + i * 256;
            int kl = q >> 4, bq = q & 15;
            *(float4*)(hst + kl*64 + bq*4) =
                *(const float4*)(hs_s + (size_t)(k0 + kl) * 64 + bq * 4);
        }
#pragma unroll
        for (int i = 0; i < 2; i++) {
            int q = tid + i * 256;
            int o = q >> 3, kq = q & 7;
            *(float4*)(wst + o*36 + kq*4) =
                *(const float4*)(fc_w + (size_t)o * D_H + k0 + kq * 4);
        }
        __syncthreads();
#pragma unroll 4
        for (int kk = 0; kk < 32; kk++) {
            u64t h0 = hst8[kk*32 + bg*2 + 0];
            u64t h1 = hst8[kk*32 + bg*2 + 1];
#pragma unroll
            for (int v = 0; v < 4; v++) {
                u64t wd = dup64(wst[(og*4 + v)*36 + kk]);
                fma2(acc[0][v], h0, wd);
                fma2(acc[1][v], h1, wd);
            }
        }
    }

    __syncthreads();
#pragma unroll
    for (int u = 0; u < 2; u++) {
#pragma unroll
        for (int v = 0; v < 4; v++) {
            float2 p = up2(acc[u][v]);
            int o  = og * 4 + v;
            int b0 = bg * 4 + u * 2;
            float bias = fc_b[o];
            L[(b0 + 0)*65 + o] = p.x + bias;
            L[(b0 + 1)*65 + o] = p.y + bias;
        }
    }
    __syncthreads();

    const int w = tid >> 5, lane = tid & 31;
#pragma unroll
    for (int rr = 0; rr < 8; rr++) {
        int b = w * 8 + rr;
        float v0 = L[b*65 + lane], v1 = L[b*65 + 32 + lane];
        float mx = fmaxf(v0, v1);
#pragma unroll
        for (int o = 16; o > 0; o >>= 1) mx = fmaxf(mx, __shfl_xor_sync(0xffffffffu, mx, o));
        float se = expf(v0 - mx) + expf(v1 - mx);
#pragma unroll
        for (int o = 16; o > 0; o >>= 1) se += __shfl_xor_sync(0xffffffffu, se, o);
        float lse = logf(se) + mx;
        float* op = out + ((size_t)b * SS + s) * D_OUT;
        op[lane]      = v0 - lse;
        op[lane + 32] = v1 - lse;
    }
}

// ==============================================================================
extern "C" void kernel_launch(void* const* d_in, const int* in_sizes, int n_in,
                              void* d_out, int out_size)
{
    (void)in_sizes; (void)n_in; (void)out_size;
    const int*   x    = (const int*)  d_in[0];
    const float* emb  = (const float*)d_in[1];
    const float* w_ih = (const float*)d_in[2];
    const float* w_hh = (const float*)d_in[3];
    const float* b_ih = (const float*)d_in[4];
    const float* b_hh = (const float*)d_in[5];
    const float* fc_w = (const float*)d_in[6];
    const float* fc_b = (const float*)d_in[7];
    float* out = (float*)d_out;

    const int rec_smem = SM_WORDS * 4;   // 131072 B
    cudaFuncSetAttribute(gru_persistent,
                         cudaFuncAttributeMaxDynamicSharedMemorySize, rec_smem);
    const int gi_smem = 2 * GBUF * 4;    // 61440 B
    cudaFuncSetAttribute(gi_hmma,
                         cudaFuncAttributeMaxDynamicSharedMemorySize, gi_smem);

    u32t *embh, *wihh, *wihl;
    cudaGetSymbolAddress((void**)&embh, g_embh);
    cudaGetSymbolAddress((void**)&wihh, g_wihh);
    cudaGetSymbolAddress((void**)&wihl, g_wihl);

    conv_hi<<<(VOCAB * 256 + 255) / 256, 256>>>(emb, embh, VOCAB * 256);
    conv_split<<<(D3H * 256 + 255) / 256, 256>>>(w_ih, wihh, wihl, D3H * 256);
    gi_hmma<<<dim3((SS * BB) / 128, D3H / 128), 256, gi_smem>>>(x, b_ih);
    gru_persistent<<<NCTA, 512, rec_smem>>>(w_hh, b_hh);
    fc_lsm<<<SS, 256>>>(fc_w, fc_b, out);
}